// round 2
// baseline (speedup 1.0000x reference)
#include <cuda_runtime.h>
#include <cuda_fp16.h>
#include <cstdint>

#define NN 10000
#define EE 160000
// log2(e)/sqrt(128) folded into Q so softmax runs in exp2 domain
#define QSCALE 0.12752532f

// ------------- device scratch (static, no allocation) -------------
__device__ float g_agg[NN * 128];
__device__ float g_h[NN * 128];
__device__ float g_ne[NN * 128];
__device__ __half g_Q[NN * 128];
__device__ __half g_K[NN * 128];
__device__ __half g_V[NN * 128];
__device__ float g_cbias[3][128];
__device__ float g_accum[128];

// ------------- helpers -------------
__device__ __forceinline__ uint32_t cvta_s(const void* p) {
    return (uint32_t)__cvta_generic_to_shared(p);
}
__device__ __forceinline__ void ldsm_x4(uint32_t& r0, uint32_t& r1, uint32_t& r2, uint32_t& r3, uint32_t a) {
    asm volatile("ldmatrix.sync.aligned.m8n8.x4.shared.b16 {%0,%1,%2,%3}, [%4];"
                 : "=r"(r0), "=r"(r1), "=r"(r2), "=r"(r3) : "r"(a));
}
__device__ __forceinline__ void ldsm_x4_t(uint32_t& r0, uint32_t& r1, uint32_t& r2, uint32_t& r3, uint32_t a) {
    asm volatile("ldmatrix.sync.aligned.m8n8.x4.trans.shared.b16 {%0,%1,%2,%3}, [%4];"
                 : "=r"(r0), "=r"(r1), "=r"(r2), "=r"(r3) : "r"(a));
}
__device__ __forceinline__ void mma_f16(float* c, const uint32_t* a, uint32_t b0, uint32_t b1) {
    asm volatile(
        "mma.sync.aligned.m16n8k16.row.col.f32.f16.f16.f32 "
        "{%0,%1,%2,%3},{%4,%5,%6,%7},{%8,%9},{%0,%1,%2,%3};\n"
        : "+f"(c[0]), "+f"(c[1]), "+f"(c[2]), "+f"(c[3])
        : "r"(a[0]), "r"(a[1]), "r"(a[2]), "r"(a[3]), "r"(b0), "r"(b1));
}
__device__ __forceinline__ uint32_t packh2(float lo, float hi) {
    __half2 h = __floats2half2_rn(lo, hi);
    return *reinterpret_cast<uint32_t*>(&h);
}

// ------------- zero scratch -------------
__global__ void zero_kernel(int zacc) {
    int i = blockIdx.x * 256 + threadIdx.x;
    if (i < NN * 128 / 4)
        ((float4*)g_agg)[i] = make_float4(0.f, 0.f, 0.f, 0.f);
    if (zacc && blockIdx.x == 0 && threadIdx.x < 128)
        g_accum[threadIdx.x] = 0.f;
}

// ------------- segment_sum(x[src], dst) -------------
__global__ void scatter_kernel(const float* __restrict__ xin, const int* __restrict__ ei, int useH) {
    const float* x = useH ? g_h : xin;
    long idx = (long)blockIdx.x * 256 + threadIdx.x;
    int e = (int)(idx >> 5);
    if (e >= EE) return;
    int q = ((int)idx & 31) * 4;
    int s = ei[e];
    int d = ei[EE + e];
    float4 v = *(const float4*)(x + (size_t)s * 128 + q);
    float* dp = g_agg + (size_t)d * 128 + q;
    asm volatile("red.global.add.v4.f32 [%0], {%1,%2,%3,%4};"
                 :: "l"(dp), "f"(v.x), "f"(v.y), "f"(v.z), "f"(v.w) : "memory");
}

// ------------- GraphConv: out = [relu](X@Wr + agg@Wl + b) -------------
// 256 thr, 64 rows x 128 cols per block, K-chunks of 32
__global__ void __launch_bounds__(256) conv_kernel(const float* __restrict__ Xin,
                                                   const float* __restrict__ Wr,
                                                   const float* __restrict__ Wl,
                                                   const float* __restrict__ bias,
                                                   int stage) {
    __shared__ float As[64 * 36];
    __shared__ float Ws[32 * 128];
    const float* X = stage ? g_h : Xin;
    float* out = stage ? g_ne : g_h;
    int relu = stage ? 0 : 1;
    int tid = threadIdx.x;
    int rbase = blockIdx.x * 64;
    int cg = (tid & 7) * 16;
    int rg = tid >> 3;
    int r0 = rg * 2, r1 = r0 + 1;
    float acc0[16], acc1[16];
#pragma unroll
    for (int j = 0; j < 16; j++) { acc0[j] = 0.f; acc1[j] = 0.f; }

    for (int pass = 0; pass < 2; pass++) {
        const float* A = pass ? g_agg : X;
        const float* W = pass ? Wl : Wr;
        for (int ks = 0; ks < 4; ks++) {
            __syncthreads();
#pragma unroll
            for (int p = 0; p < 2; p++) {
                int slot = tid + p * 256;
                int ar = slot >> 3, ac = slot & 7;
                float4 v = make_float4(0.f, 0.f, 0.f, 0.f);
                int gr = rbase + ar;
                if (gr < NN) v = *(const float4*)(A + (size_t)gr * 128 + ks * 32 + ac * 4);
                *(float4*)(As + ar * 36 + ac * 4) = v;
            }
#pragma unroll
            for (int p = 0; p < 4; p++) {
                int slot = tid + p * 256;
                int wr = slot >> 5, wc = slot & 31;
                *(float4*)(Ws + wr * 128 + wc * 4) =
                    *(const float4*)(W + (size_t)(ks * 32 + wr) * 128 + wc * 4);
            }
            __syncthreads();
#pragma unroll
            for (int kk = 0; kk < 32; kk++) {
                float a0 = As[r0 * 36 + kk], a1 = As[r1 * 36 + kk];
#pragma unroll
                for (int j = 0; j < 16; j++) {
                    float wv = Ws[kk * 128 + cg + j];
                    acc0[j] += a0 * wv;
                    acc1[j] += a1 * wv;
                }
            }
        }
    }
    int gr0 = rbase + r0, gr1 = rbase + r1;
    float4 o0[4], o1[4];
#pragma unroll
    for (int q = 0; q < 4; q++) {
        float b0 = bias[cg + 4 * q + 0], b1 = bias[cg + 4 * q + 1];
        float b2 = bias[cg + 4 * q + 2], b3 = bias[cg + 4 * q + 3];
        o0[q] = make_float4(acc0[4 * q] + b0, acc0[4 * q + 1] + b1, acc0[4 * q + 2] + b2, acc0[4 * q + 3] + b3);
        o1[q] = make_float4(acc1[4 * q] + b0, acc1[4 * q + 1] + b1, acc1[4 * q + 2] + b2, acc1[4 * q + 3] + b3);
        if (relu) {
            o0[q].x = fmaxf(o0[q].x, 0.f); o0[q].y = fmaxf(o0[q].y, 0.f);
            o0[q].z = fmaxf(o0[q].z, 0.f); o0[q].w = fmaxf(o0[q].w, 0.f);
            o1[q].x = fmaxf(o1[q].x, 0.f); o1[q].y = fmaxf(o1[q].y, 0.f);
            o1[q].z = fmaxf(o1[q].z, 0.f); o1[q].w = fmaxf(o1[q].w, 0.f);
        }
    }
#pragma unroll
    for (int q = 0; q < 4; q++) {
        if (gr0 < NN) *(float4*)(out + (size_t)gr0 * 128 + cg + 4 * q) = o0[q];
        if (gr1 < NN) *(float4*)(out + (size_t)gr1 * 128 + cg + 4 * q) = o1[q];
    }
}

// ------------- combined bias: b + global@Wg + bg -------------
__global__ void bias_kernel(const float* __restrict__ g,
                            const float* bQ, const float* bQg, const float* WQg,
                            const float* bK, const float* bKg, const float* WKg,
                            const float* bV, const float* bVg, const float* WVg) {
    int m = blockIdx.x, c = threadIdx.x;
    const float* b = m == 0 ? bQ : (m == 1 ? bK : bV);
    const float* bg = m == 0 ? bQg : (m == 1 ? bKg : bVg);
    const float* Wg = m == 0 ? WQg : (m == 1 ? WKg : WVg);
    float s = b[c] + bg[c];
    for (int i = 0; i < 64; i++) s += g[i] * Wg[i * 128 + c];
    g_cbias[m][c] = s;
}

// ------------- QKV: out_h = (ne@W + cbias) * scale -> fp16 -------------
__global__ void __launch_bounds__(256) qkv_kernel(const float* __restrict__ WQ,
                                                  const float* __restrict__ WK,
                                                  const float* __restrict__ WV) {
    __shared__ float As[64 * 36];
    __shared__ float Ws[32 * 128];
    int m = blockIdx.y;
    const float* W = m == 0 ? WQ : (m == 1 ? WK : WV);
    __half* out = m == 0 ? g_Q : (m == 1 ? g_K : g_V);
    float scale = m == 0 ? QSCALE : 1.0f;
    int tid = threadIdx.x;
    int rbase = blockIdx.x * 64;
    int cg = (tid & 7) * 16;
    int rg = tid >> 3;
    int r0 = rg * 2, r1 = r0 + 1;
    float acc0[16], acc1[16];
#pragma unroll
    for (int j = 0; j < 16; j++) { acc0[j] = 0.f; acc1[j] = 0.f; }

    for (int ks = 0; ks < 4; ks++) {
        __syncthreads();
#pragma unroll
        for (int p = 0; p < 2; p++) {
            int slot = tid + p * 256;
            int ar = slot >> 3, ac = slot & 7;
            float4 v = make_float4(0.f, 0.f, 0.f, 0.f);
            int gr = rbase + ar;
            if (gr < NN) v = *(const float4*)(g_ne + (size_t)gr * 128 + ks * 32 + ac * 4);
            *(float4*)(As + ar * 36 + ac * 4) = v;
        }
#pragma unroll
        for (int p = 0; p < 4; p++) {
            int slot = tid + p * 256;
            int wr = slot >> 5, wc = slot & 31;
            *(float4*)(Ws + wr * 128 + wc * 4) =
                *(const float4*)(W + (size_t)(ks * 32 + wr) * 128 + wc * 4);
        }
        __syncthreads();
#pragma unroll
        for (int kk = 0; kk < 32; kk++) {
            float a0 = As[r0 * 36 + kk], a1 = As[r1 * 36 + kk];
#pragma unroll
            for (int j = 0; j < 16; j++) {
                float wv = Ws[kk * 128 + cg + j];
                acc0[j] += a0 * wv;
                acc1[j] += a1 * wv;
            }
        }
    }
    int gr0 = rbase + r0, gr1 = rbase + r1;
    __half h0[16], h1[16];
#pragma unroll
    for (int j = 0; j < 16; j++) {
        float cb = g_cbias[m][cg + j];
        h0[j] = __float2half_rn((acc0[j] + cb) * scale);
        h1[j] = __float2half_rn((acc1[j] + cb) * scale);
    }
    if (gr0 < NN) {
        *(uint4*)(out + (size_t)gr0 * 128 + cg) = *(uint4*)h0;
        *(uint4*)(out + (size_t)gr0 * 128 + cg + 8) = *(uint4*)(h0 + 8);
    }
    if (gr1 < NN) {
        *(uint4*)(out + (size_t)gr1 * 128 + cg) = *(uint4*)h1;
        *(uint4*)(out + (size_t)gr1 * 128 + cg + 8) = *(uint4*)(h1 + 8);
    }
}

// ------------- flash attention, column-sum of softmax(QK^T)V -------------
#define KSTR 272  // smem row stride (bytes) for half tiles: 256 + 16 pad

__global__ void __launch_bounds__(128, 1) attn_kernel() {
    extern __shared__ char sm[];
    __half* Qs = (__half*)sm;                       // 64 * 272B
    __half* Ks = (__half*)(sm + 64 * KSTR);         // 128 * 272B
    __half* Vs = (__half*)(sm + 64 * KSTR + 128 * KSTR);
    float* stage = (float*)(sm + 64 * KSTR);        // reused after loop
    int tid = threadIdx.x, lane = tid & 31, w = tid >> 5;
    int rbase = blockIdx.x * 64;

    // load Q tile (invalid rows -> 0)
    for (int i = tid; i < 64 * 16; i += 128) {
        int r = i >> 4, ch = i & 15;
        int gr = rbase + r;
        uint4 v = make_uint4(0u, 0u, 0u, 0u);
        if (gr < NN) v = *(const uint4*)((const char*)g_Q + (size_t)gr * 256 + ch * 16);
        *(uint4*)((char*)Qs + r * KSTR + ch * 16) = v;
    }
    __syncthreads();

    // preload Q a-frags: 8 k-tiles x 4 regs
    uint32_t qa[8][4];
    {
        int g = lane >> 3, idx = lane & 7;
#pragma unroll
        for (int kt = 0; kt < 8; kt++) {
            int row = w * 16 + (g & 1) * 8 + idx;
            uint32_t a = cvta_s((char*)Qs + row * KSTR + kt * 32 + (g >> 1) * 16);
            ldsm_x4(qa[kt][0], qa[kt][1], qa[kt][2], qa[kt][3], a);
        }
    }

    float M0 = -1e30f, M1 = -1e30f, l0 = 0.f, l1 = 0.f;
    float o[64];
#pragma unroll
    for (int i = 0; i < 64; i++) o[i] = 0.f;

    for (int jb = 0; jb < NN; jb += 128) {
        __syncthreads();
        // load K,V chunk (invalid rows -> 0)
        for (int i = tid; i < 2 * 128 * 16; i += 128) {
            int sel = i >= 128 * 16;
            int ii = sel ? i - 128 * 16 : i;
            int r = ii >> 4, ch = ii & 15;
            int gr = jb + r;
            uint4 v = make_uint4(0u, 0u, 0u, 0u);
            const char* src = sel ? (const char*)g_V : (const char*)g_K;
            if (gr < NN) v = *(const uint4*)(src + (size_t)gr * 256 + ch * 16);
            char* dst = sel ? (char*)Vs : (char*)Ks;
            *(uint4*)(dst + r * KSTR + ch * 16) = v;
        }
        __syncthreads();

        float s[64];
#pragma unroll
        for (int i = 0; i < 64; i++) s[i] = 0.f;

        // S = Q @ K^T
        {
            int g = lane >> 3, idx = lane & 7;
#pragma unroll
            for (int kt = 0; kt < 8; kt++) {
#pragma unroll
                for (int nt2 = 0; nt2 < 8; nt2++) {
                    int row = nt2 * 16 + (g & 2) * 4 + idx;
                    uint32_t a = cvta_s((char*)Ks + row * KSTR + kt * 32 + (g & 1) * 16);
                    uint32_t b0, b1, b2, b3;
                    ldsm_x4(b0, b1, b2, b3, a);
                    mma_f16(s + (2 * nt2) * 4, qa[kt], b0, b1);
                    mma_f16(s + (2 * nt2 + 1) * 4, qa[kt], b2, b3);
                }
            }
        }

        // mask tail keys
        if (jb + 128 > NN) {
#pragma unroll
            for (int nt = 0; nt < 16; nt++) {
                int j0 = jb + nt * 8 + 2 * (lane & 3);
                if (j0 >= NN) { s[nt * 4 + 0] = -1e30f; s[nt * 4 + 2] = -1e30f; }
                if (j0 + 1 >= NN) { s[nt * 4 + 1] = -1e30f; s[nt * 4 + 3] = -1e30f; }
            }
        }

        // online softmax (exp2 domain)
        float m0 = -1e30f, m1 = -1e30f;
#pragma unroll
        for (int nt = 0; nt < 16; nt++) {
            m0 = fmaxf(m0, fmaxf(s[nt * 4 + 0], s[nt * 4 + 1]));
            m1 = fmaxf(m1, fmaxf(s[nt * 4 + 2], s[nt * 4 + 3]));
        }
        m0 = fmaxf(m0, __shfl_xor_sync(0xffffffffu, m0, 1));
        m0 = fmaxf(m0, __shfl_xor_sync(0xffffffffu, m0, 2));
        m1 = fmaxf(m1, __shfl_xor_sync(0xffffffffu, m1, 1));
        m1 = fmaxf(m1, __shfl_xor_sync(0xffffffffu, m1, 2));
        float Mn0 = fmaxf(M0, m0), Mn1 = fmaxf(M1, m1);
        float sc0 = exp2f(M0 - Mn0), sc1 = exp2f(M1 - Mn1);
        M0 = Mn0; M1 = Mn1;
        float r0 = 0.f, r1 = 0.f;
#pragma unroll
        for (int nt = 0; nt < 16; nt++) {
            s[nt * 4 + 0] = exp2f(s[nt * 4 + 0] - M0);
            s[nt * 4 + 1] = exp2f(s[nt * 4 + 1] - M0);
            s[nt * 4 + 2] = exp2f(s[nt * 4 + 2] - M1);
            s[nt * 4 + 3] = exp2f(s[nt * 4 + 3] - M1);
            r0 += s[nt * 4 + 0] + s[nt * 4 + 1];
            r1 += s[nt * 4 + 2] + s[nt * 4 + 3];
        }
        r0 += __shfl_xor_sync(0xffffffffu, r0, 1);
        r0 += __shfl_xor_sync(0xffffffffu, r0, 2);
        r1 += __shfl_xor_sync(0xffffffffu, r1, 1);
        r1 += __shfl_xor_sync(0xffffffffu, r1, 2);
        l0 = l0 * sc0 + r0;
        l1 = l1 * sc1 + r1;
#pragma unroll
        for (int nt = 0; nt < 16; nt++) {
            o[nt * 4 + 0] *= sc0; o[nt * 4 + 1] *= sc0;
            o[nt * 4 + 2] *= sc1; o[nt * 4 + 3] *= sc1;
        }

        // O += P @ V
        {
            int g = lane >> 3, idx = lane & 7;
#pragma unroll
            for (int kt = 0; kt < 8; kt++) {
                uint32_t pa[4];
                pa[0] = packh2(s[8 * kt + 0], s[8 * kt + 1]);
                pa[1] = packh2(s[8 * kt + 2], s[8 * kt + 3]);
                pa[2] = packh2(s[8 * kt + 4], s[8 * kt + 5]);
                pa[3] = packh2(s[8 * kt + 6], s[8 * kt + 7]);
#pragma unroll
                for (int nt2 = 0; nt2 < 8; nt2++) {
                    int row = kt * 16 + (g & 1) * 8 + idx;
                    uint32_t a = cvta_s((char*)Vs + row * KSTR + nt2 * 32 + (g >> 1) * 16);
                    uint32_t b0, b1, b2, b3;
                    ldsm_x4_t(b0, b1, b2, b3, a);
                    mma_f16(o + (2 * nt2) * 4, pa, b0, b1);
                    mma_f16(o + (2 * nt2 + 1) * 4, pa, b2, b3);
                }
            }
        }
    }

    // normalize, stage rows, column-sum -> g_accum
    float inv0 = 1.f / l0, inv1 = 1.f / l1;
    __syncthreads();
    int rr0 = w * 16 + (lane >> 2);
#pragma unroll
    for (int nt = 0; nt < 16; nt++) {
        int c = nt * 8 + 2 * (lane & 3);
        stage[rr0 * 129 + c] = o[nt * 4 + 0] * inv0;
        stage[rr0 * 129 + c + 1] = o[nt * 4 + 1] * inv0;
        stage[(rr0 + 8) * 129 + c] = o[nt * 4 + 2] * inv1;
        stage[(rr0 + 8) * 129 + c + 1] = o[nt * 4 + 3] * inv1;
    }
    __syncthreads();
    int c = tid;
    float acc = 0.f;
    int nv = min(64, NN - rbase);
    for (int r = 0; r < nv; r++) acc += stage[r * 129 + c];
    atomicAdd(&g_accum[c], acc);
}

// ------------- mean -> Wo -> MLP -> softmax -------------
__global__ void __launch_bounds__(128) final_kernel(const float* Wo, const float* bo,
                                                    const float* W1, const float* b1v,
                                                    const float* W2, const float* b2v,
                                                    const float* W3, const float* b3v,
                                                    float* out) {
    __shared__ float v0[128], v1[128], v2[64], v3[32], red[2];
    int t = threadIdx.x;
    v0[t] = g_accum[t] * (1.0f / NN);
    __syncthreads();
    float s = bo[t];
    for (int i = 0; i < 128; i++) s += v0[i] * Wo[i * 128 + t];
    v1[t] = s;
    __syncthreads();
    if (t < 64) {
        float s2 = b1v[t];
        for (int i = 0; i < 128; i++) s2 += v1[i] * W1[i * 64 + t];
        v2[t] = fmaxf(s2, 0.f);
    }
    __syncthreads();
    if (t < 32) {
        float s3 = b2v[t];
        for (int i = 0; i < 64; i++) s3 += v2[i] * W2[i * 32 + t];
        v3[t] = fmaxf(s3, 0.f);
    }
    __syncthreads();
    float lg = b3v[t];
    for (int i = 0; i < 32; i++) lg += v3[i] * W3[i * 128 + t];
    v1[t] = lg;
    __syncthreads();
    if (t == 0) {
        float mx = -1e30f;
        for (int i = 0; i < 128; i++) mx = fmaxf(mx, v1[i]);
        float sm = 0.f;
        for (int i = 0; i < 128; i++) sm += expf(v1[i] - mx);
        red[0] = mx; red[1] = sm;
    }
    __syncthreads();
    out[t] = expf(lg - red[0]) / red[1];
}

// ------------- launch -------------
extern "C" void kernel_launch(void* const* d_in, const int* in_sizes, int n_in,
                              void* d_out, int out_size) {
    const float* nf = (const float*)d_in[0];
    const float* gi = (const float*)d_in[1];
    const int* ei = (const int*)d_in[2];
    const float* W1_root = (const float*)d_in[3];
    const float* W1_rel = (const float*)d_in[4];
    const float* b1 = (const float*)d_in[5];
    const float* W2_root = (const float*)d_in[6];
    const float* W2_rel = (const float*)d_in[7];
    const float* b2 = (const float*)d_in[8];
    const float* WQ = (const float*)d_in[9];
    const float* bQ = (const float*)d_in[10];
    const float* WK = (const float*)d_in[11];
    const float* bK = (const float*)d_in[12];
    const float* WV = (const float*)d_in[13];
    const float* bV = (const float*)d_in[14];
    const float* WQg = (const float*)d_in[15];
    const float* bQg = (const float*)d_in[16];
    const float* WKg = (const float*)d_in[17];
    const float* bKg = (const float*)d_in[18];
    const float* WVg = (const float*)d_in[19];
    const float* bVg = (const float*)d_in[20];
    const float* Wo = (const float*)d_in[21];
    const float* bo = (const float*)d_in[22];
    const float* Wfc1 = (const float*)d_in[23];
    const float* bfc1 = (const float*)d_in[24];
    const float* Wfc2 = (const float*)d_in[25];
    const float* bfc2 = (const float*)d_in[26];
    const float* Wfc3 = (const float*)d_in[27];
    const float* bfc3 = (const float*)d_in[28];

    static int attr_set = 0;
    if (!attr_set) {
        cudaFuncSetAttribute(attn_kernel, cudaFuncAttributeMaxDynamicSharedMemorySize, 90112);
        attr_set = 1;
    }

    zero_kernel<<<1250, 256>>>(1);
    scatter_kernel<<<20000, 256>>>(nf, ei, 0);
    conv_kernel<<<157, 256>>>(nf, W1_root, W1_rel, b1, 0);
    zero_kernel<<<1250, 256>>>(0);
    scatter_kernel<<<20000, 256>>>(nf, ei, 1);
    conv_kernel<<<157, 256>>>(nf, W2_root, W2_rel, b2, 1);
    bias_kernel<<<3, 128>>>(gi, bQ, bQg, WQg, bK, bKg, WKg, bV, bVg, WVg);
    qkv_kernel<<<dim3(157, 3), 256>>>(WQ, WK, WV);
    attn_kernel<<<157, 128, 87040>>>();
    final_kernel<<<1, 128>>>(Wo, bo, Wfc1, bfc1, Wfc2, bfc2, Wfc3, bfc3, (float*)d_out);
}

// round 3
// speedup vs baseline: 1.2790x; 1.2790x over previous
#include <cuda_runtime.h>
#include <cuda_fp16.h>
#include <cstdint>

#define NN 10000
#define EE 160000
// log2(e)/sqrt(128) folded into Q so softmax runs in exp2 domain
#define QSCALE 0.12752532f

#define NSPLIT 8
#define CHUNK 1280
#define NQT 79          // ceil(10000/128) Q tiles

// ------------- device scratch (static, no allocation) -------------
__device__ float g_agg[NN * 128];
__device__ float g_h[NN * 128];
__device__ float g_ne[NN * 128];
__device__ __half g_Q[NN * 128];
__device__ __half g_K[NN * 128];
__device__ __half g_V[NN * 128];
__device__ float g_cbias[3][128];
__device__ float g_accum[128];
__device__ float g_pm[NQT * NSPLIT * 128];
__device__ float g_pl[NQT * NSPLIT * 128];
__device__ float g_po[(size_t)NQT * NSPLIT * 128 * 128];   // 41.4 MB

// ------------- helpers -------------
__device__ __forceinline__ uint32_t cvta_s(const void* p) {
    return (uint32_t)__cvta_generic_to_shared(p);
}
__device__ __forceinline__ void ldsm_x4(uint32_t& r0, uint32_t& r1, uint32_t& r2, uint32_t& r3, uint32_t a) {
    asm volatile("ldmatrix.sync.aligned.m8n8.x4.shared.b16 {%0,%1,%2,%3}, [%4];"
                 : "=r"(r0), "=r"(r1), "=r"(r2), "=r"(r3) : "r"(a));
}
__device__ __forceinline__ void ldsm_x4_t(uint32_t& r0, uint32_t& r1, uint32_t& r2, uint32_t& r3, uint32_t a) {
    asm volatile("ldmatrix.sync.aligned.m8n8.x4.trans.shared.b16 {%0,%1,%2,%3}, [%4];"
                 : "=r"(r0), "=r"(r1), "=r"(r2), "=r"(r3) : "r"(a));
}
__device__ __forceinline__ void mma_f16(float* c, const uint32_t* a, uint32_t b0, uint32_t b1) {
    asm volatile(
        "mma.sync.aligned.m16n8k16.row.col.f32.f16.f16.f32 "
        "{%0,%1,%2,%3},{%4,%5,%6,%7},{%8,%9},{%0,%1,%2,%3};\n"
        : "+f"(c[0]), "+f"(c[1]), "+f"(c[2]), "+f"(c[3])
        : "r"(a[0]), "r"(a[1]), "r"(a[2]), "r"(a[3]), "r"(b0), "r"(b1));
}
__device__ __forceinline__ uint32_t packh2(float lo, float hi) {
    __half2 h = __floats2half2_rn(lo, hi);
    return *reinterpret_cast<uint32_t*>(&h);
}
__device__ __forceinline__ void cp_async16(uint32_t s, const void* g) {
    asm volatile("cp.async.cg.shared.global [%0], [%1], 16;" :: "r"(s), "l"(g));
}
__device__ __forceinline__ void cp_commit() { asm volatile("cp.async.commit_group;"); }
template <int N> __device__ __forceinline__ void cp_wait() {
    asm volatile("cp.async.wait_group %0;" :: "n"(N));
}

// ------------- zero scratch -------------
__global__ void zero_kernel(int zacc) {
    int i = blockIdx.x * 256 + threadIdx.x;
    if (i < NN * 128 / 4)
        ((float4*)g_agg)[i] = make_float4(0.f, 0.f, 0.f, 0.f);
    if (zacc && blockIdx.x == 0 && threadIdx.x < 128)
        g_accum[threadIdx.x] = 0.f;
}

// ------------- segment_sum(x[src], dst) -------------
__global__ void scatter_kernel(const float* __restrict__ xin, const int* __restrict__ ei, int useH) {
    const float* x = useH ? g_h : xin;
    long idx = (long)blockIdx.x * 256 + threadIdx.x;
    int e = (int)(idx >> 5);
    if (e >= EE) return;
    int q = ((int)idx & 31) * 4;
    int s = ei[e];
    int d = ei[EE + e];
    float4 v = *(const float4*)(x + (size_t)s * 128 + q);
    float* dp = g_agg + (size_t)d * 128 + q;
    asm volatile("red.global.add.v4.f32 [%0], {%1,%2,%3,%4};"
                 :: "l"(dp), "f"(v.x), "f"(v.y), "f"(v.z), "f"(v.w) : "memory");
}

// ------------- GraphConv: out = [relu](X@Wr + agg@Wl + b) -------------
__global__ void __launch_bounds__(256) conv_kernel(const float* __restrict__ Xin,
                                                   const float* __restrict__ Wr,
                                                   const float* __restrict__ Wl,
                                                   const float* __restrict__ bias,
                                                   int stage) {
    __shared__ float As[64 * 36];
    __shared__ float Ws[32 * 128];
    const float* X = stage ? g_h : Xin;
    float* out = stage ? g_ne : g_h;
    int relu = stage ? 0 : 1;
    int tid = threadIdx.x;
    int rbase = blockIdx.x * 64;
    int cg = (tid & 7) * 16;
    int rg = tid >> 3;
    int r0 = rg * 2, r1 = r0 + 1;
    float acc0[16], acc1[16];
#pragma unroll
    for (int j = 0; j < 16; j++) { acc0[j] = 0.f; acc1[j] = 0.f; }

    for (int pass = 0; pass < 2; pass++) {
        const float* A = pass ? g_agg : X;
        const float* W = pass ? Wl : Wr;
        for (int ks = 0; ks < 4; ks++) {
            __syncthreads();
#pragma unroll
            for (int p = 0; p < 2; p++) {
                int slot = tid + p * 256;
                int ar = slot >> 3, ac = slot & 7;
                float4 v = make_float4(0.f, 0.f, 0.f, 0.f);
                int gr = rbase + ar;
                if (gr < NN) v = *(const float4*)(A + (size_t)gr * 128 + ks * 32 + ac * 4);
                *(float4*)(As + ar * 36 + ac * 4) = v;
            }
#pragma unroll
            for (int p = 0; p < 4; p++) {
                int slot = tid + p * 256;
                int wr = slot >> 5, wc = slot & 31;
                *(float4*)(Ws + wr * 128 + wc * 4) =
                    *(const float4*)(W + (size_t)(ks * 32 + wr) * 128 + wc * 4);
            }
            __syncthreads();
#pragma unroll
            for (int kk = 0; kk < 32; kk++) {
                float a0 = As[r0 * 36 + kk], a1 = As[r1 * 36 + kk];
#pragma unroll
                for (int j = 0; j < 16; j++) {
                    float wv = Ws[kk * 128 + cg + j];
                    acc0[j] += a0 * wv;
                    acc1[j] += a1 * wv;
                }
            }
        }
    }
    int gr0 = rbase + r0, gr1 = rbase + r1;
    float4 o0[4], o1[4];
#pragma unroll
    for (int q = 0; q < 4; q++) {
        float b0 = bias[cg + 4 * q + 0], b1 = bias[cg + 4 * q + 1];
        float b2 = bias[cg + 4 * q + 2], b3 = bias[cg + 4 * q + 3];
        o0[q] = make_float4(acc0[4 * q] + b0, acc0[4 * q + 1] + b1, acc0[4 * q + 2] + b2, acc0[4 * q + 3] + b3);
        o1[q] = make_float4(acc1[4 * q] + b0, acc1[4 * q + 1] + b1, acc1[4 * q + 2] + b2, acc1[4 * q + 3] + b3);
        if (relu) {
            o0[q].x = fmaxf(o0[q].x, 0.f); o0[q].y = fmaxf(o0[q].y, 0.f);
            o0[q].z = fmaxf(o0[q].z, 0.f); o0[q].w = fmaxf(o0[q].w, 0.f);
            o1[q].x = fmaxf(o1[q].x, 0.f); o1[q].y = fmaxf(o1[q].y, 0.f);
            o1[q].z = fmaxf(o1[q].z, 0.f); o1[q].w = fmaxf(o1[q].w, 0.f);
        }
    }
#pragma unroll
    for (int q = 0; q < 4; q++) {
        if (gr0 < NN) *(float4*)(out + (size_t)gr0 * 128 + cg + 4 * q) = o0[q];
        if (gr1 < NN) *(float4*)(out + (size_t)gr1 * 128 + cg + 4 * q) = o1[q];
    }
}

// ------------- combined bias: b + global@Wg + bg -------------
__global__ void bias_kernel(const float* __restrict__ g,
                            const float* bQ, const float* bQg, const float* WQg,
                            const float* bK, const float* bKg, const float* WKg,
                            const float* bV, const float* bVg, const float* WVg) {
    int m = blockIdx.x, c = threadIdx.x;
    const float* b = m == 0 ? bQ : (m == 1 ? bK : bV);
    const float* bg = m == 0 ? bQg : (m == 1 ? bKg : bVg);
    const float* Wg = m == 0 ? WQg : (m == 1 ? WKg : WVg);
    float s = b[c] + bg[c];
    for (int i = 0; i < 64; i++) s += g[i] * Wg[i * 128 + c];
    g_cbias[m][c] = s;
}

// ------------- QKV: out_h = (ne@W + cbias) * scale -> fp16 -------------
__global__ void __launch_bounds__(256) qkv_kernel(const float* __restrict__ WQ,
                                                  const float* __restrict__ WK,
                                                  const float* __restrict__ WV) {
    __shared__ float As[64 * 36];
    __shared__ float Ws[32 * 128];
    int m = blockIdx.y;
    const float* W = m == 0 ? WQ : (m == 1 ? WK : WV);
    __half* out = m == 0 ? g_Q : (m == 1 ? g_K : g_V);
    float scale = m == 0 ? QSCALE : 1.0f;
    int tid = threadIdx.x;
    int rbase = blockIdx.x * 64;
    int cg = (tid & 7) * 16;
    int rg = tid >> 3;
    int r0 = rg * 2, r1 = r0 + 1;
    float acc0[16], acc1[16];
#pragma unroll
    for (int j = 0; j < 16; j++) { acc0[j] = 0.f; acc1[j] = 0.f; }

    for (int ks = 0; ks < 4; ks++) {
        __syncthreads();
#pragma unroll
        for (int p = 0; p < 2; p++) {
            int slot = tid + p * 256;
            int ar = slot >> 3, ac = slot & 7;
            float4 v = make_float4(0.f, 0.f, 0.f, 0.f);
            int gr = rbase + ar;
            if (gr < NN) v = *(const float4*)(g_ne + (size_t)gr * 128 + ks * 32 + ac * 4);
            *(float4*)(As + ar * 36 + ac * 4) = v;
        }
#pragma unroll
        for (int p = 0; p < 4; p++) {
            int slot = tid + p * 256;
            int wr = slot >> 5, wc = slot & 31;
            *(float4*)(Ws + wr * 128 + wc * 4) =
                *(const float4*)(W + (size_t)(ks * 32 + wr) * 128 + wc * 4);
        }
        __syncthreads();
#pragma unroll
        for (int kk = 0; kk < 32; kk++) {
            float a0 = As[r0 * 36 + kk], a1 = As[r1 * 36 + kk];
#pragma unroll
            for (int j = 0; j < 16; j++) {
                float wv = Ws[kk * 128 + cg + j];
                acc0[j] += a0 * wv;
                acc1[j] += a1 * wv;
            }
        }
    }
    int gr0 = rbase + r0, gr1 = rbase + r1;
    __half h0[16], h1[16];
#pragma unroll
    for (int j = 0; j < 16; j++) {
        float cb = g_cbias[m][cg + j];
        h0[j] = __float2half_rn((acc0[j] + cb) * scale);
        h1[j] = __float2half_rn((acc1[j] + cb) * scale);
    }
    if (gr0 < NN) {
        *(uint4*)(out + (size_t)gr0 * 128 + cg) = *(uint4*)h0;
        *(uint4*)(out + (size_t)gr0 * 128 + cg + 8) = *(uint4*)(h0 + 8);
    }
    if (gr1 < NN) {
        *(uint4*)(out + (size_t)gr1 * 128 + cg) = *(uint4*)h1;
        *(uint4*)(out + (size_t)gr1 * 128 + cg + 8) = *(uint4*)(h1 + 8);
    }
}

// ------------- split-KV flash attention -------------
// grid = 79 Qtiles x 8 KV-splits; block = 256 (8 warps x 16 rows)
// smem: Q 128*272 | stage0 {K 128*272, V 128*272} | stage1 {K,V}
#define KSTR 272
#define SM_Q 0
#define SM_ST (128 * KSTR)
#define STAGE_BYTES (2 * 128 * KSTR)
#define SMEM_TOTAL (128 * KSTR + 2 * STAGE_BYTES)

__global__ void __launch_bounds__(256, 1) attn_kernel() {
    extern __shared__ char sm[];
    __half* Qs = (__half*)(sm + SM_Q);
    int tid = threadIdx.x, lane = tid & 31, w = tid >> 5;
    int unit = blockIdx.x;
    int qtile = unit / NSPLIT, split = unit - qtile * NSPLIT;
    int rbase = qtile * 128;
    int kv0 = split * CHUNK;
    int kv1 = min(kv0 + CHUNK, NN);
    int niter = (kv1 - kv0 + 127) >> 7;

    // load Q tile (OOB rows clamped; excluded at merge)
    for (int i = tid; i < 128 * 16; i += 256) {
        int r = i >> 4, ch = i & 15;
        int gr = min(rbase + r, NN - 1);
        *(uint4*)((char*)Qs + r * KSTR + ch * 16) =
            *(const uint4*)((const char*)g_Q + (size_t)gr * 256 + ch * 16);
    }

    // issue stage 0 K/V loads
    {
        int jb = kv0;
#pragma unroll
        for (int p = 0; p < 16; p++) {
            int i = p * 256 + tid;
            int sel = i >= 2048;
            int ii = i & 2047;
            int r = ii >> 4, ch = ii & 15;
            int gr = min(jb + r, NN - 1);
            const char* src = sel ? (const char*)g_V : (const char*)g_K;
            uint32_t dst = cvta_s(sm + SM_ST + (sel ? 128 * KSTR : 0) + r * KSTR + ch * 16);
            cp_async16(dst, src + (size_t)gr * 256 + ch * 16);
        }
        cp_commit();
    }
    __syncthreads();

    // preload Q a-frags
    uint32_t qa[8][4];
    {
        int g = lane >> 3, idx = lane & 7;
#pragma unroll
        for (int kt = 0; kt < 8; kt++) {
            int row = w * 16 + (g & 1) * 8 + idx;
            uint32_t a = cvta_s((char*)Qs + row * KSTR + kt * 32 + (g >> 1) * 16);
            ldsm_x4(qa[kt][0], qa[kt][1], qa[kt][2], qa[kt][3], a);
        }
    }

    float M0 = -1e30f, M1 = -1e30f, l0 = 0.f, l1 = 0.f;
    float o[64];
#pragma unroll
    for (int i = 0; i < 64; i++) o[i] = 0.f;

    for (int it = 0; it < niter; it++) {
        int jb = kv0 + it * 128;
        char* stg = sm + SM_ST + (it & 1) * STAGE_BYTES;
        __half* Ks = (__half*)stg;
        __half* Vs = (__half*)(stg + 128 * KSTR);

        // prefetch next stage
        if (it + 1 < niter) {
            int jn = jb + 128;
            char* nstg = sm + SM_ST + ((it + 1) & 1) * STAGE_BYTES;
#pragma unroll
            for (int p = 0; p < 16; p++) {
                int i = p * 256 + tid;
                int sel = i >= 2048;
                int ii = i & 2047;
                int r = ii >> 4, ch = ii & 15;
                int gr = min(jn + r, NN - 1);
                const char* src = sel ? (const char*)g_V : (const char*)g_K;
                uint32_t dst = cvta_s(nstg + (sel ? 128 * KSTR : 0) + r * KSTR + ch * 16);
                cp_async16(dst, src + (size_t)gr * 256 + ch * 16);
            }
            cp_commit();
            cp_wait<1>();
        } else {
            cp_wait<0>();
        }
        __syncthreads();

        float s[64];
#pragma unroll
        for (int i = 0; i < 64; i++) s[i] = 0.f;

        // S = Q @ K^T
        {
            int g = lane >> 3, idx = lane & 7;
#pragma unroll
            for (int kt = 0; kt < 8; kt++) {
#pragma unroll
                for (int nt2 = 0; nt2 < 8; nt2++) {
                    int row = nt2 * 16 + (g & 2) * 4 + idx;
                    uint32_t a = cvta_s((char*)Ks + row * KSTR + kt * 32 + (g & 1) * 16);
                    uint32_t b0, b1, b2, b3;
                    ldsm_x4(b0, b1, b2, b3, a);
                    mma_f16(s + (2 * nt2) * 4, qa[kt], b0, b1);
                    mma_f16(s + (2 * nt2 + 1) * 4, qa[kt], b2, b3);
                }
            }
        }

        // mask tail keys
        if (jb + 128 > kv1) {
#pragma unroll
            for (int nt = 0; nt < 16; nt++) {
                int j0 = jb + nt * 8 + 2 * (lane & 3);
                if (j0 >= kv1) { s[nt * 4 + 0] = -1e30f; s[nt * 4 + 2] = -1e30f; }
                if (j0 + 1 >= kv1) { s[nt * 4 + 1] = -1e30f; s[nt * 4 + 3] = -1e30f; }
            }
        }

        // online softmax (exp2 domain)
        float m0 = -1e30f, m1 = -1e30f;
#pragma unroll
        for (int nt = 0; nt < 16; nt++) {
            m0 = fmaxf(m0, fmaxf(s[nt * 4 + 0], s[nt * 4 + 1]));
            m1 = fmaxf(m1, fmaxf(s[nt * 4 + 2], s[nt * 4 + 3]));
        }
        m0 = fmaxf(m0, __shfl_xor_sync(0xffffffffu, m0, 1));
        m0 = fmaxf(m0, __shfl_xor_sync(0xffffffffu, m0, 2));
        m1 = fmaxf(m1, __shfl_xor_sync(0xffffffffu, m1, 1));
        m1 = fmaxf(m1, __shfl_xor_sync(0xffffffffu, m1, 2));
        float Mn0 = fmaxf(M0, m0), Mn1 = fmaxf(M1, m1);
        float sc0 = exp2f(M0 - Mn0), sc1 = exp2f(M1 - Mn1);
        M0 = Mn0; M1 = Mn1;
        float r0 = 0.f, r1 = 0.f;
#pragma unroll
        for (int nt = 0; nt < 16; nt++) {
            s[nt * 4 + 0] = exp2f(s[nt * 4 + 0] - M0);
            s[nt * 4 + 1] = exp2f(s[nt * 4 + 1] - M0);
            s[nt * 4 + 2] = exp2f(s[nt * 4 + 2] - M1);
            s[nt * 4 + 3] = exp2f(s[nt * 4 + 3] - M1);
            r0 += s[nt * 4 + 0] + s[nt * 4 + 1];
            r1 += s[nt * 4 + 2] + s[nt * 4 + 3];
        }
        r0 += __shfl_xor_sync(0xffffffffu, r0, 1);
        r0 += __shfl_xor_sync(0xffffffffu, r0, 2);
        r1 += __shfl_xor_sync(0xffffffffu, r1, 1);
        r1 += __shfl_xor_sync(0xffffffffu, r1, 2);
        l0 = l0 * sc0 + r0;
        l1 = l1 * sc1 + r1;
#pragma unroll
        for (int nt = 0; nt < 16; nt++) {
            o[nt * 4 + 0] *= sc0; o[nt * 4 + 1] *= sc0;
            o[nt * 4 + 2] *= sc1; o[nt * 4 + 3] *= sc1;
        }

        // O += P @ V
        {
            int g = lane >> 3, idx = lane & 7;
#pragma unroll
            for (int kt = 0; kt < 8; kt++) {
                uint32_t pa[4];
                pa[0] = packh2(s[8 * kt + 0], s[8 * kt + 1]);
                pa[1] = packh2(s[8 * kt + 2], s[8 * kt + 3]);
                pa[2] = packh2(s[8 * kt + 4], s[8 * kt + 5]);
                pa[3] = packh2(s[8 * kt + 6], s[8 * kt + 7]);
#pragma unroll
                for (int nt2 = 0; nt2 < 8; nt2++) {
                    int row = kt * 16 + (g & 1) * 8 + idx;
                    uint32_t a = cvta_s((char*)Vs + row * KSTR + nt2 * 32 + (g >> 1) * 16);
                    uint32_t b0, b1, b2, b3;
                    ldsm_x4_t(b0, b1, b2, b3, a);
                    mma_f16(o + (2 * nt2) * 4, pa, b0, b1);
                    mma_f16(o + (2 * nt2 + 1) * 4, pa, b2, b3);
                }
            }
        }
        __syncthreads();
    }

    // write partials: rows r0 = w*16 + (lane>>2), r0+8 (unnormalized o, plus m, l)
    int rr0 = w * 16 + (lane >> 2);
    int rr1 = rr0 + 8;
    size_t ubase = (size_t)unit * 128;
    if ((lane & 3) == 0) {
        g_pm[ubase + rr0] = M0;
        g_pl[ubase + rr0] = l0;
        g_pm[ubase + rr1] = M1;
        g_pl[ubase + rr1] = l1;
    }
#pragma unroll
    for (int nt = 0; nt < 16; nt++) {
        int c = nt * 8 + 2 * (lane & 3);
        *(float2*)&g_po[(ubase + rr0) * 128 + c] = make_float2(o[nt * 4 + 0], o[nt * 4 + 1]);
        *(float2*)&g_po[(ubase + rr1) * 128 + c] = make_float2(o[nt * 4 + 2], o[nt * 4 + 3]);
    }
}

// ------------- merge splits + column mean-sum -------------
__global__ void __launch_bounds__(128) merge_kernel() {
    int c = threadIdx.x;
    int rstart = blockIdx.x * 16;
    float acc = 0.f;
    for (int i = 0; i < 16; i++) {
        int r = rstart + i;
        if (r >= NN) break;
        int tile = r >> 7, row = r & 127;
        int base = tile * (NSPLIT * 128) + row;
        float M = -1e30f;
#pragma unroll
        for (int s = 0; s < NSPLIT; s++) M = fmaxf(M, g_pm[base + s * 128]);
        float L = 0.f, oc = 0.f;
#pragma unroll
        for (int s = 0; s < NSPLIT; s++) {
            float sc = exp2f(g_pm[base + s * 128] - M);
            L += g_pl[base + s * 128] * sc;
            oc += g_po[(size_t)(base + s * 128) * 128 + c] * sc;
        }
        acc += oc / L;
    }
    atomicAdd(&g_accum[c], acc);
}

// ------------- mean -> Wo -> MLP -> softmax -------------
__global__ void __launch_bounds__(128) final_kernel(const float* Wo, const float* bo,
                                                    const float* W1, const float* b1v,
                                                    const float* W2, const float* b2v,
                                                    const float* W3, const float* b3v,
                                                    float* out) {
    __shared__ float v0[128], v1[128], v2[64], v3[32], red[2];
    int t = threadIdx.x;
    v0[t] = g_accum[t] * (1.0f / NN);
    __syncthreads();
    float s = bo[t];
    for (int i = 0; i < 128; i++) s += v0[i] * Wo[i * 128 + t];
    v1[t] = s;
    __syncthreads();
    if (t < 64) {
        float s2 = b1v[t];
        for (int i = 0; i < 128; i++) s2 += v1[i] * W1[i * 64 + t];
        v2[t] = fmaxf(s2, 0.f);
    }
    __syncthreads();
    if (t < 32) {
        float s3 = b2v[t];
        for (int i = 0; i < 64; i++) s3 += v2[i] * W2[i * 32 + t];
        v3[t] = fmaxf(s3, 0.f);
    }
    __syncthreads();
    float lg = b3v[t];
    for (int i = 0; i < 32; i++) lg += v3[i] * W3[i * 128 + t];
    v1[t] = lg;
    __syncthreads();
    if (t == 0) {
        float mx = -1e30f;
        for (int i = 0; i < 128; i++) mx = fmaxf(mx, v1[i]);
        float sm = 0.f;
        for (int i = 0; i < 128; i++) sm += expf(v1[i] - mx);
        red[0] = mx; red[1] = sm;
    }
    __syncthreads();
    out[t] = expf(lg - red[0]) / red[1];
}

// ------------- launch -------------
extern "C" void kernel_launch(void* const* d_in, const int* in_sizes, int n_in,
                              void* d_out, int out_size) {
    const float* nf = (const float*)d_in[0];
    const float* gi = (const float*)d_in[1];
    const int* ei = (const int*)d_in[2];
    const float* W1_root = (const float*)d_in[3];
    const float* W1_rel = (const float*)d_in[4];
    const float* b1 = (const float*)d_in[5];
    const float* W2_root = (const float*)d_in[6];
    const float* W2_rel = (const float*)d_in[7];
    const float* b2 = (const float*)d_in[8];
    const float* WQ = (const float*)d_in[9];
    const float* bQ = (const float*)d_in[10];
    const float* WK = (const float*)d_in[11];
    const float* bK = (const float*)d_in[12];
    const float* WV = (const float*)d_in[13];
    const float* bV = (const float*)d_in[14];
    const float* WQg = (const float*)d_in[15];
    const float* bQg = (const float*)d_in[16];
    const float* WKg = (const float*)d_in[17];
    const float* bKg = (const float*)d_in[18];
    const float* WVg = (const float*)d_in[19];
    const float* bVg = (const float*)d_in[20];
    const float* Wo = (const float*)d_in[21];
    const float* bo = (const float*)d_in[22];
    const float* Wfc1 = (const float*)d_in[23];
    const float* bfc1 = (const float*)d_in[24];
    const float* Wfc2 = (const float*)d_in[25];
    const float* bfc2 = (const float*)d_in[26];
    const float* Wfc3 = (const float*)d_in[27];
    const float* bfc3 = (const float*)d_in[28];

    static int attr_set = 0;
    if (!attr_set) {
        cudaFuncSetAttribute(attn_kernel, cudaFuncAttributeMaxDynamicSharedMemorySize, SMEM_TOTAL);
        attr_set = 1;
    }

    zero_kernel<<<1250, 256>>>(1);
    scatter_kernel<<<20000, 256>>>(nf, ei, 0);
    conv_kernel<<<157, 256>>>(nf, W1_root, W1_rel, b1, 0);
    zero_kernel<<<1250, 256>>>(0);
    scatter_kernel<<<20000, 256>>>(nf, ei, 1);
    conv_kernel<<<157, 256>>>(nf, W2_root, W2_rel, b2, 1);
    bias_kernel<<<3, 128>>>(gi, bQ, bQg, WQg, bK, bKg, WKg, bV, bVg, WVg);
    qkv_kernel<<<dim3(157, 3), 256>>>(WQ, WK, WV);
    attn_kernel<<<NQT * NSPLIT, 256, SMEM_TOTAL>>>();
    merge_kernel<<<625, 128>>>();
    final_kernel<<<1, 128>>>(Wo, bo, Wfc1, bfc1, Wfc2, bfc2, Wfc3, bfc3, (float*)d_out);
}